// round 2
// baseline (speedup 1.0000x reference)
#include <cuda_runtime.h>
#include <math.h>

#define NV 100000
#define NE 3200000

// ---------------- scratch (device globals: allocation-free) ----------------
__device__ int   g_is64;
__device__ float g_dinv[NV];
__device__ int   g_indeg[NV];
__device__ int   g_rowptr[NV + 1];
__device__ int   g_cursor[NV];
__device__ int   g_col[NE];
__device__ float g_a [NV * 128];   // aggregated features (128-dim)
__device__ float g_h [NV * 128];   // hidden (128-dim)
__device__ float g_x1[NV * 512];   // 512-dim buffer A
__device__ float g_x2[NV * 512];   // 512-dim buffer B

// ---------------- dtype detection (int64 vs int32 edge_index) --------------
__global__ void k_detect(const int* ei32) {
    // If edge_index is int64 (values < 2^31), every odd int32 word is 0.
    __shared__ int nz;
    if (threadIdx.x == 0) nz = 0;
    __syncthreads();
    int c = 0;
    for (int i = threadIdx.x; i < 2048; i += blockDim.x)
        if (ei32[2 * i + 1] != 0) c = 1;
    if (c) atomicExch(&nz, 1);
    __syncthreads();
    if (threadIdx.x == 0) g_is64 = (nz == 0) ? 1 : 0;
}

__device__ __forceinline__ int edge_val(const void* ei, long long idx) {
    if (g_is64) return (int)((const long long*)ei)[idx];
    return ((const int*)ei)[idx];
}

// ---------------- degree / CSR build ----------------
__global__ void k_init_indeg() {
    int i = blockIdx.x * blockDim.x + threadIdx.x;
    if (i < NV) g_indeg[i] = 0;
}

__global__ void k_hist(const void* ei) {
    int e = blockIdx.x * blockDim.x + threadIdx.x;
    if (e >= NE) return;
    int d = edge_val(ei, (long long)NE + e);
    atomicAdd(&g_indeg[d], 1);
}

__global__ void k_dinv() {
    int i = blockIdx.x * blockDim.x + threadIdx.x;
    if (i < NV) g_dinv[i] = rsqrtf((float)(g_indeg[i] + 1));  // +1 self-loop
}

// Single-block exclusive scan of indeg -> rowptr (and cursor copy).
__global__ void k_scan() {
    __shared__ int s[1024];
    int base = 0;
    for (int start = 0; start < NV; start += 1024) {
        int i = start + threadIdx.x;
        int v = (i < NV) ? g_indeg[i] : 0;
        s[threadIdx.x] = v;
        __syncthreads();
        for (int off = 1; off < 1024; off <<= 1) {
            int t = (threadIdx.x >= off) ? s[threadIdx.x - off] : 0;
            __syncthreads();
            s[threadIdx.x] += t;
            __syncthreads();
        }
        int incl = s[threadIdx.x];
        int total = s[1023];
        if (i < NV) {
            int ex = base + incl - v;
            g_rowptr[i] = ex;
            g_cursor[i] = ex;
        }
        base += total;
        __syncthreads();
    }
    if (threadIdx.x == 0) g_rowptr[NV] = base;
}

__global__ void k_fill(const void* ei) {
    int e = blockIdx.x * blockDim.x + threadIdx.x;
    if (e >= NE) return;
    int sidx = edge_val(ei, e);
    int d    = edge_val(ei, (long long)NE + e);
    int p = atomicAdd(&g_cursor[d], 1);
    g_col[p] = sidx;
}

// ---------------- 128-dim symmetric-normalized aggregation ----------------
// out[v] = dinv[v]^2 * in[v] + sum_{e: dst=v} dinv[v]*dinv[src]*in[src]
__global__ void __launch_bounds__(128) k_agg(const float* __restrict__ xin,
                                             float* __restrict__ xout) {
    int v = blockIdx.x;
    int f = threadIdx.x;
    float dv = g_dinv[v];
    float acc = dv * dv * xin[v * 128 + f];
    int e  = g_rowptr[v];
    int e1 = g_rowptr[v + 1];
    for (; e + 3 < e1; e += 4) {
        int s0 = g_col[e], s1 = g_col[e + 1], s2 = g_col[e + 2], s3 = g_col[e + 3];
        float w0 = g_dinv[s0], w1 = g_dinv[s1], w2 = g_dinv[s2], w3 = g_dinv[s3];
        float v0 = xin[s0 * 128 + f], v1 = xin[s1 * 128 + f];
        float v2 = xin[s2 * 128 + f], v3 = xin[s3 * 128 + f];
        acc += dv * (w0 * v0 + w1 * v1 + w2 * v2 + w3 * v3);
    }
    for (; e < e1; e++) {
        int s = g_col[e];
        acc += dv * g_dinv[s] * xin[s * 128 + f];
    }
    xout[v * 128 + f] = acc;
}

// ---------------- SGEMM: C[M,N] = A[M,K] @ B[K,N] + bias (+ReLU) ----------
template <bool RELU>
__global__ void __launch_bounds__(256) k_sgemm(const float* __restrict__ A,
                                               const float* __restrict__ B,
                                               const float* __restrict__ bias,
                                               float* __restrict__ C,
                                               int M, int K, int N) {
    __shared__ float As[8][128];
    __shared__ float Bs[8][128];
    int tid = threadIdx.x;
    int m0 = blockIdx.y * 128, n0 = blockIdx.x * 128;
    int tx = tid % 16, ty = tid / 16;

    float acc[8][8];
#pragma unroll
    for (int i = 0; i < 8; i++)
#pragma unroll
        for (int j = 0; j < 8; j++) acc[i][j] = 0.f;

    int arow = tid >> 1;        // 0..127
    int acol = (tid & 1) * 4;   // 0 or 4
    int brow = tid >> 5;        // 0..7
    int bcol = (tid & 31) * 4;  // 0..124

    for (int k0 = 0; k0 < K; k0 += 8) {
        float4 av;
        if (m0 + arow < M)
            av = *(const float4*)&A[(size_t)(m0 + arow) * K + k0 + acol];
        else
            av = make_float4(0.f, 0.f, 0.f, 0.f);
        As[acol + 0][arow] = av.x;
        As[acol + 1][arow] = av.y;
        As[acol + 2][arow] = av.z;
        As[acol + 3][arow] = av.w;
        *(float4*)&Bs[brow][bcol] =
            *(const float4*)&B[(size_t)(k0 + brow) * N + n0 + bcol];
        __syncthreads();
#pragma unroll
        for (int k = 0; k < 8; k++) {
            float a[8], b[8];
#pragma unroll
            for (int i = 0; i < 8; i++) a[i] = As[k][ty * 8 + i];
#pragma unroll
            for (int j = 0; j < 8; j++) b[j] = Bs[k][tx * 8 + j];
#pragma unroll
            for (int i = 0; i < 8; i++)
#pragma unroll
                for (int j = 0; j < 8; j++) acc[i][j] += a[i] * b[j];
        }
        __syncthreads();
    }

#pragma unroll
    for (int i = 0; i < 8; i++) {
        int m = m0 + ty * 8 + i;
        if (m >= M) continue;
#pragma unroll
        for (int j = 0; j < 8; j += 4) {
            int n = n0 + tx * 8 + j;
            float4 r;
            r.x = acc[i][j + 0] + bias[n + 0];
            r.y = acc[i][j + 1] + bias[n + 1];
            r.z = acc[i][j + 2] + bias[n + 2];
            r.w = acc[i][j + 3] + bias[n + 3];
            if (RELU) {
                r.x = fmaxf(r.x, 0.f); r.y = fmaxf(r.y, 0.f);
                r.z = fmaxf(r.z, 0.f); r.w = fmaxf(r.w, 0.f);
            }
            *(float4*)&C[(size_t)m * N + n] = r;
        }
    }
}

// ---------------- final projection 512 -> 3 ----------------
__global__ void __launch_bounds__(256) k_out3(const float* __restrict__ h,
                                              const float* __restrict__ Wc,
                                              const float* __restrict__ bc,
                                              float* __restrict__ out) {
    __shared__ float wc[512 * 3];
    for (int i = threadIdx.x; i < 512 * 3; i += blockDim.x) wc[i] = Wc[i];
    __syncthreads();
    int gw   = (blockIdx.x * blockDim.x + threadIdx.x) >> 5;  // global warp = node
    int lane = threadIdx.x & 31;
    if (gw >= NV) return;
    float a0 = 0.f, a1 = 0.f, a2 = 0.f;
#pragma unroll
    for (int i = 0; i < 16; i++) {
        int k = lane + 32 * i;
        float hv = h[gw * 512 + k];
        a0 += hv * wc[k * 3 + 0];
        a1 += hv * wc[k * 3 + 1];
        a2 += hv * wc[k * 3 + 2];
    }
#pragma unroll
    for (int o = 16; o; o >>= 1) {
        a0 += __shfl_xor_sync(0xFFFFFFFFu, a0, o);
        a1 += __shfl_xor_sync(0xFFFFFFFFu, a1, o);
        a2 += __shfl_xor_sync(0xFFFFFFFFu, a2, o);
    }
    if (lane == 0) {
        out[gw * 3 + 0] = a0 + bc[0];
        out[gw * 3 + 1] = a1 + bc[1];
        out[gw * 3 + 2] = a2 + bc[2];
    }
}

// ---------------- launch ----------------
extern "C" void kernel_launch(void* const* d_in, const int* in_sizes, int n_in,
                              void* d_out, int out_size) {
    const float* x  = (const float*)d_in[0];
    const void*  ei = d_in[1];
    const float* W1 = (const float*)d_in[2];
    const float* b1 = (const float*)d_in[3];
    const float* W2 = (const float*)d_in[4];
    const float* b2 = (const float*)d_in[5];
    const float* W3 = (const float*)d_in[6];
    const float* b3 = (const float*)d_in[7];
    const float* Wi = (const float*)d_in[8];
    const float* bi = (const float*)d_in[9];
    const float* Wc = (const float*)d_in[10];
    const float* bc = (const float*)d_in[11];
    float* out = (float*)d_out;

    float *pA, *pH, *pX1, *pX2;
    cudaGetSymbolAddress((void**)&pA,  g_a);
    cudaGetSymbolAddress((void**)&pH,  g_h);
    cudaGetSymbolAddress((void**)&pX1, g_x1);
    cudaGetSymbolAddress((void**)&pX2, g_x2);

    const int TB = 256;
    const int NVB = (NV + TB - 1) / TB;
    const int NEB = (NE + TB - 1) / TB;

    // preprocessing: dtype detect, degrees, CSR
    k_detect<<<1, 256>>>((const int*)ei);
    k_init_indeg<<<NVB, TB>>>();
    k_hist<<<NEB, TB>>>(ei);
    k_dinv<<<NVB, TB>>>();
    k_scan<<<1, 1024>>>();
    k_fill<<<NEB, TB>>>(ei);

    // layer 1: agg(x) @ W1 + b1, relu
    k_agg<<<NV, 128>>>(x, pA);
    k_sgemm<true><<<dim3(1, (NV + 127) / 128), 256>>>(pA, W1, b1, pH, NV, 128, 128);
    // layer 2
    k_agg<<<NV, 128>>>(pH, pA);
    k_sgemm<true><<<dim3(1, (NV + 127) / 128), 256>>>(pA, W2, b2, pH, NV, 128, 128);
    // layer 3: agg in 128-dim, project 128->512
    k_agg<<<NV, 128>>>(pH, pA);
    k_sgemm<true><<<dim3(4, (NV + 127) / 128), 256>>>(pA, W3, b3, pX1, NV, 128, 512);
    // MLP 512->512, relu
    k_sgemm<true><<<dim3(4, (NV + 127) / 128), 256>>>(pX1, Wi, bi, pX2, NV, 512, 512);
    // classifier 512->3
    k_out3<<<(NV * 32 + TB - 1) / TB, TB>>>(pX2, Wc, bc, out);
}

// round 3
// speedup vs baseline: 1.1388x; 1.1388x over previous
#include <cuda_runtime.h>
#include <mma.h>
#include <math.h>

using namespace nvcuda;

#define NV 100000
#define NE 3200000

// ---------------- scratch (device globals: allocation-free) ----------------
__device__ int   g_is64;
__device__ float g_dinv[NV];
__device__ int   g_indeg[NV];
__device__ int   g_rowptr[NV + 1];
__device__ int   g_cursor[NV];
__device__ int   g_col[NE];
__device__ float g_a [NV * 128];   // aggregated features (128-dim)
__device__ float g_h [NV * 128];   // hidden (128-dim)
__device__ float g_x1[NV * 512];   // 512-dim buffer A
__device__ float g_x2[NV * 512];   // 512-dim buffer B

// ---------------- dtype detection (int64 vs int32 edge_index) --------------
__global__ void k_detect(const int* ei32) {
    __shared__ int nz;
    if (threadIdx.x == 0) nz = 0;
    __syncthreads();
    int c = 0;
    for (int i = threadIdx.x; i < 2048; i += blockDim.x)
        if (ei32[2 * i + 1] != 0) c = 1;
    if (c) atomicExch(&nz, 1);
    __syncthreads();
    if (threadIdx.x == 0) g_is64 = (nz == 0) ? 1 : 0;
}

__device__ __forceinline__ int edge_val(const void* ei, long long idx) {
    if (g_is64) return (int)((const long long*)ei)[idx];
    return ((const int*)ei)[idx];
}

// ---------------- degree / CSR build ----------------
__global__ void k_init_indeg() {
    int i = blockIdx.x * blockDim.x + threadIdx.x;
    if (i < NV) g_indeg[i] = 0;
}

__global__ void k_hist(const void* ei) {
    int e = blockIdx.x * blockDim.x + threadIdx.x;
    if (e >= NE) return;
    int d = edge_val(ei, (long long)NE + e);
    atomicAdd(&g_indeg[d], 1);
}

__global__ void k_dinv() {
    int i = blockIdx.x * blockDim.x + threadIdx.x;
    if (i < NV) g_dinv[i] = rsqrtf((float)(g_indeg[i] + 1));  // +1 self-loop
}

// Single-block exclusive scan of indeg -> rowptr (and cursor copy).
__global__ void k_scan() {
    __shared__ int s[1024];
    int base = 0;
    for (int start = 0; start < NV; start += 1024) {
        int i = start + threadIdx.x;
        int v = (i < NV) ? g_indeg[i] : 0;
        s[threadIdx.x] = v;
        __syncthreads();
        for (int off = 1; off < 1024; off <<= 1) {
            int t = (threadIdx.x >= off) ? s[threadIdx.x - off] : 0;
            __syncthreads();
            s[threadIdx.x] += t;
            __syncthreads();
        }
        int incl = s[threadIdx.x];
        int total = s[1023];
        if (i < NV) {
            int ex = base + incl - v;
            g_rowptr[i] = ex;
            g_cursor[i] = ex;
        }
        base += total;
        __syncthreads();
    }
    if (threadIdx.x == 0) g_rowptr[NV] = base;
}

__global__ void k_fill(const void* ei) {
    int e = blockIdx.x * blockDim.x + threadIdx.x;
    if (e >= NE) return;
    int sidx = edge_val(ei, e);
    int d    = edge_val(ei, (long long)NE + e);
    int p = atomicAdd(&g_cursor[d], 1);
    g_col[p] = sidx;
}

// ---------------- 128-dim symmetric-normalized aggregation ----------------
__global__ void __launch_bounds__(128) k_agg(const float* __restrict__ xin,
                                             float* __restrict__ xout) {
    int v = blockIdx.x;
    int f = threadIdx.x;
    float dv = g_dinv[v];
    float acc = dv * dv * xin[v * 128 + f];
    int e  = g_rowptr[v];
    int e1 = g_rowptr[v + 1];
    for (; e + 3 < e1; e += 4) {
        int s0 = g_col[e], s1 = g_col[e + 1], s2 = g_col[e + 2], s3 = g_col[e + 3];
        float w0 = g_dinv[s0], w1 = g_dinv[s1], w2 = g_dinv[s2], w3 = g_dinv[s3];
        float v0 = xin[s0 * 128 + f], v1 = xin[s1 * 128 + f];
        float v2 = xin[s2 * 128 + f], v3 = xin[s3 * 128 + f];
        acc += dv * (w0 * v0 + w1 * v1 + w2 * v2 + w3 * v3);
    }
    for (; e < e1; e++) {
        int s = g_col[e];
        acc += dv * g_dinv[s] * xin[s * 128 + f];
    }
    xout[v * 128 + f] = acc;
}

// ---------------- TF32 tensor-core GEMM: C = A[M,K] @ B[K,N] + bias (+ReLU)
// Block tile 128x128, BK=32, 8 warps (4 along M x 2 along N), each warp 32x64.
template <bool RELU>
__global__ void __launch_bounds__(256) k_tgemm(const float* __restrict__ A,
                                               const float* __restrict__ B,
                                               const float* __restrict__ bias,
                                               float* __restrict__ C,
                                               int M, int K, int N) {
    constexpr int BM = 128, BN = 128, BK = 32;
    constexpr int LDA = BK + 4;   // 36 (multiple of 4 floats -> 16B aligned rows)
    constexpr int LDB = BN + 4;   // 132
    __shared__ float As[BM * LDA];
    __shared__ float Bs[BK * LDB];
    __shared__ float stage[8][16 * 20];   // per-warp 16x16 staging, ld=20

    int tid  = threadIdx.x;
    int warp = tid >> 5;
    int lane = tid & 31;
    int m0 = blockIdx.y * BM, n0 = blockIdx.x * BN;
    int wm = warp & 3;   // 0..3 along M (32 rows each)
    int wn = warp >> 2;  // 0..1 along N (64 cols each)

    wmma::fragment<wmma::accumulator, 16, 16, 8, float> acc[2][4];
#pragma unroll
    for (int i = 0; i < 2; i++)
#pragma unroll
        for (int j = 0; j < 4; j++) wmma::fill_fragment(acc[i][j], 0.0f);

    for (int k0 = 0; k0 < K; k0 += BK) {
        // load A tile 128x32: 1024 float4, 4 per thread
#pragma unroll
        for (int i = 0; i < 4; i++) {
            int f = tid + 256 * i;
            int r = f >> 3;
            int c = (f & 7) * 4;
            float4 v;
            if (m0 + r < M)
                v = *(const float4*)&A[(size_t)(m0 + r) * K + k0 + c];
            else
                v = make_float4(0.f, 0.f, 0.f, 0.f);
            float* p = &As[r * LDA + c];
            p[0] = wmma::__float_to_tf32(v.x);
            p[1] = wmma::__float_to_tf32(v.y);
            p[2] = wmma::__float_to_tf32(v.z);
            p[3] = wmma::__float_to_tf32(v.w);
        }
        // load B tile 32x128: 1024 float4, 4 per thread (K,N multiples of 32/128)
#pragma unroll
        for (int i = 0; i < 4; i++) {
            int f = tid + 256 * i;
            int r = f >> 5;
            int c = (f & 31) * 4;
            float4 v = *(const float4*)&B[(size_t)(k0 + r) * N + n0 + c];
            float* p = &Bs[r * LDB + c];
            p[0] = wmma::__float_to_tf32(v.x);
            p[1] = wmma::__float_to_tf32(v.y);
            p[2] = wmma::__float_to_tf32(v.z);
            p[3] = wmma::__float_to_tf32(v.w);
        }
        __syncthreads();

#pragma unroll
        for (int kk = 0; kk < BK; kk += 8) {
            wmma::fragment<wmma::matrix_a, 16, 16, 8, wmma::precision::tf32,
                           wmma::row_major> af[2];
            wmma::fragment<wmma::matrix_b, 16, 16, 8, wmma::precision::tf32,
                           wmma::row_major> bf[4];
#pragma unroll
            for (int i = 0; i < 2; i++)
                wmma::load_matrix_sync(af[i], &As[(wm * 32 + i * 16) * LDA + kk], LDA);
#pragma unroll
            for (int j = 0; j < 4; j++)
                wmma::load_matrix_sync(bf[j], &Bs[kk * LDB + wn * 64 + j * 16], LDB);
#pragma unroll
            for (int i = 0; i < 2; i++)
#pragma unroll
                for (int j = 0; j < 4; j++)
                    wmma::mma_sync(acc[i][j], af[i], bf[j], acc[i][j]);
        }
        __syncthreads();
    }

    // epilogue: stage each 16x16 fragment in smem, apply bias+relu, float4 out
#pragma unroll
    for (int i = 0; i < 2; i++) {
#pragma unroll
        for (int j = 0; j < 4; j++) {
            wmma::store_matrix_sync(&stage[warp][0], acc[i][j], 20,
                                    wmma::mem_row_major);
            __syncwarp();
            int r  = lane >> 1;            // 0..15
            int cs = (lane & 1) * 8;       // 0 or 8
            int gm = m0 + wm * 32 + i * 16 + r;
            int gn = n0 + wn * 64 + j * 16 + cs;
            if (gm < M) {
                float4 o0, o1;
                const float* sp = &stage[warp][r * 20 + cs];
                o0.x = sp[0] + bias[gn + 0];
                o0.y = sp[1] + bias[gn + 1];
                o0.z = sp[2] + bias[gn + 2];
                o0.w = sp[3] + bias[gn + 3];
                o1.x = sp[4] + bias[gn + 4];
                o1.y = sp[5] + bias[gn + 5];
                o1.z = sp[6] + bias[gn + 6];
                o1.w = sp[7] + bias[gn + 7];
                if (RELU) {
                    o0.x = fmaxf(o0.x, 0.f); o0.y = fmaxf(o0.y, 0.f);
                    o0.z = fmaxf(o0.z, 0.f); o0.w = fmaxf(o0.w, 0.f);
                    o1.x = fmaxf(o1.x, 0.f); o1.y = fmaxf(o1.y, 0.f);
                    o1.z = fmaxf(o1.z, 0.f); o1.w = fmaxf(o1.w, 0.f);
                }
                *(float4*)&C[(size_t)gm * N + gn]     = o0;
                *(float4*)&C[(size_t)gm * N + gn + 4] = o1;
            }
            __syncwarp();
        }
    }
}

// ---------------- final projection 512 -> 3 ----------------
__global__ void __launch_bounds__(256) k_out3(const float* __restrict__ h,
                                              const float* __restrict__ Wc,
                                              const float* __restrict__ bc,
                                              float* __restrict__ out) {
    __shared__ float wc[512 * 3];
    for (int i = threadIdx.x; i < 512 * 3; i += blockDim.x) wc[i] = Wc[i];
    __syncthreads();
    int gw   = (blockIdx.x * blockDim.x + threadIdx.x) >> 5;  // global warp = node
    int lane = threadIdx.x & 31;
    if (gw >= NV) return;
    float a0 = 0.f, a1 = 0.f, a2 = 0.f;
#pragma unroll
    for (int i = 0; i < 16; i++) {
        int k = lane + 32 * i;
        float hv = h[gw * 512 + k];
        a0 += hv * wc[k * 3 + 0];
        a1 += hv * wc[k * 3 + 1];
        a2 += hv * wc[k * 3 + 2];
    }
#pragma unroll
    for (int o = 16; o; o >>= 1) {
        a0 += __shfl_xor_sync(0xFFFFFFFFu, a0, o);
        a1 += __shfl_xor_sync(0xFFFFFFFFu, a1, o);
        a2 += __shfl_xor_sync(0xFFFFFFFFu, a2, o);
    }
    if (lane == 0) {
        out[gw * 3 + 0] = a0 + bc[0];
        out[gw * 3 + 1] = a1 + bc[1];
        out[gw * 3 + 2] = a2 + bc[2];
    }
}

// ---------------- launch ----------------
extern "C" void kernel_launch(void* const* d_in, const int* in_sizes, int n_in,
                              void* d_out, int out_size) {
    const float* x  = (const float*)d_in[0];
    const void*  ei = d_in[1];
    const float* W1 = (const float*)d_in[2];
    const float* b1 = (const float*)d_in[3];
    const float* W2 = (const float*)d_in[4];
    const float* b2 = (const float*)d_in[5];
    const float* W3 = (const float*)d_in[6];
    const float* b3 = (const float*)d_in[7];
    const float* Wi = (const float*)d_in[8];
    const float* bi = (const float*)d_in[9];
    const float* Wc = (const float*)d_in[10];
    const float* bc = (const float*)d_in[11];
    float* out = (float*)d_out;

    float *pA, *pH, *pX1, *pX2;
    cudaGetSymbolAddress((void**)&pA,  g_a);
    cudaGetSymbolAddress((void**)&pH,  g_h);
    cudaGetSymbolAddress((void**)&pX1, g_x1);
    cudaGetSymbolAddress((void**)&pX2, g_x2);

    const int TB = 256;
    const int NVB = (NV + TB - 1) / TB;
    const int NEB = (NE + TB - 1) / TB;
    const int MT  = (NV + 127) / 128;

    // preprocessing: dtype detect, degrees, CSR
    k_detect<<<1, 256>>>((const int*)ei);
    k_init_indeg<<<NVB, TB>>>();
    k_hist<<<NEB, TB>>>(ei);
    k_dinv<<<NVB, TB>>>();
    k_scan<<<1, 1024>>>();
    k_fill<<<NEB, TB>>>(ei);

    // layer 1: agg(x) @ W1 + b1, relu
    k_agg<<<NV, 128>>>(x, pA);
    k_tgemm<true><<<dim3(1, MT), 256>>>(pA, W1, b1, pH, NV, 128, 128);
    // layer 2
    k_agg<<<NV, 128>>>(pH, pA);
    k_tgemm<true><<<dim3(1, MT), 256>>>(pA, W2, b2, pH, NV, 128, 128);
    // layer 3: agg in 128-dim, project 128->512
    k_agg<<<NV, 128>>>(pH, pA);
    k_tgemm<true><<<dim3(4, MT), 256>>>(pA, W3, b3, pX1, NV, 128, 512);
    // MLP 512->512, relu
    k_tgemm<true><<<dim3(4, MT), 256>>>(pX1, Wi, bi, pX2, NV, 512, 512);
    // classifier 512->3
    k_out3<<<(NV * 32 + TB - 1) / TB, TB>>>(pX2, Wc, bc, out);
}

// round 7
// speedup vs baseline: 1.7617x; 1.5470x over previous
#include <cuda_runtime.h>
#include <cstdint>
#include <mma.h>
#include <math.h>

using namespace nvcuda;

#define NV 100000
#define NE 3200000
#define NBLK 391          // ceil(NV/256)

// ---------------- scratch (device globals: allocation-free) ----------------
__device__ int   g_is64;
__device__ float g_dinv[NV];
__device__ int   g_indeg[NV];
__device__ int   g_rowptr[NV + 1];
__device__ int   g_cursor[NV];
__device__ int   g_bsum[NBLK];
__device__ int   g_boff[NBLK];
__device__ int   g_col[NE];
__device__ float g_a [NV * 128];   // aggregated features (128-dim)
__device__ float g_h [NV * 128];   // hidden (128-dim)
__device__ float g_x1[NV * 512];   // 512-dim buffer A
__device__ float g_x2[NV * 512];   // 512-dim buffer B

// ---------------- init + dtype detection (fused) ---------------------------
__global__ void k_init_detect(const int* ei32) {
    int i = blockIdx.x * blockDim.x + threadIdx.x;
    if (i < NV) g_indeg[i] = 0;
    if (blockIdx.x == 0) {
        __shared__ int nz;
        if (threadIdx.x == 0) nz = 0;
        __syncthreads();
        int c = 0;
        for (int k = threadIdx.x; k < 2048; k += blockDim.x)
            if (ei32[2 * k + 1] != 0) c = 1;
        if (c) atomicExch(&nz, 1);
        __syncthreads();
        if (threadIdx.x == 0) g_is64 = (nz == 0) ? 1 : 0;
    }
}

__device__ __forceinline__ int edge_val(const void* ei, long long idx) {
    if (g_is64) return (int)((const long long*)ei)[idx];
    return ((const int*)ei)[idx];
}

// ---------------- degree histogram ----------------
__global__ void k_hist(const void* ei) {
    int e = blockIdx.x * blockDim.x + threadIdx.x;
    if (e >= NE) return;
    int d = edge_val(ei, (long long)NE + e);
    atomicAdd(&g_indeg[d], 1);
}

// ---------------- 3-phase scan (reduce / scan block sums / scatter) --------
__global__ void __launch_bounds__(256) k_reduce() {
    int i = blockIdx.x * 256 + threadIdx.x;
    int v = (i < NV) ? g_indeg[i] : 0;
#pragma unroll
    for (int o = 16; o; o >>= 1) v += __shfl_xor_sync(0xFFFFFFFFu, v, o);
    __shared__ int ws[8];
    if ((threadIdx.x & 31) == 0) ws[threadIdx.x >> 5] = v;
    __syncthreads();
    if (threadIdx.x == 0) {
        int s = 0;
#pragma unroll
        for (int j = 0; j < 8; j++) s += ws[j];
        g_bsum[blockIdx.x] = s;
    }
}

__global__ void __launch_bounds__(512) k_scanb() {
    int t = threadIdx.x;
    int v = (t < NBLK) ? g_bsum[t] : 0;
    int incl = v;
#pragma unroll
    for (int o = 1; o < 32; o <<= 1) {
        int n = __shfl_up_sync(0xFFFFFFFFu, incl, o);
        if ((t & 31) >= o) incl += n;
    }
    __shared__ int ws[16];
    if ((t & 31) == 31) ws[t >> 5] = incl;
    __syncthreads();
    if (t == 0) {
        int run = 0;
#pragma unroll
        for (int j = 0; j < 16; j++) { int x = ws[j]; ws[j] = run; run += x; }
    }
    __syncthreads();
    if (t < NBLK) g_boff[t] = incl - v + ws[t >> 5];
}

__global__ void __launch_bounds__(256) k_scatter() {
    int b = blockIdx.x, t = threadIdx.x;
    int i = b * 256 + t;
    int v = (i < NV) ? g_indeg[i] : 0;
    int incl = v;
#pragma unroll
    for (int o = 1; o < 32; o <<= 1) {
        int n = __shfl_up_sync(0xFFFFFFFFu, incl, o);
        if ((t & 31) >= o) incl += n;
    }
    __shared__ int ws[8];
    if ((t & 31) == 31) ws[t >> 5] = incl;
    __syncthreads();
    if (t == 0) {
        int run = 0;
#pragma unroll
        for (int j = 0; j < 8; j++) { int x = ws[j]; ws[j] = run; run += x; }
    }
    __syncthreads();
    int ex = incl - v + ws[t >> 5] + g_boff[b];
    if (i < NV) {
        g_rowptr[i] = ex;
        g_cursor[i] = ex;
        g_dinv[i]   = rsqrtf((float)(v + 1));   // +1 self-loop
        if (i == NV - 1) g_rowptr[NV] = ex + v;
    }
}

__global__ void k_fill(const void* ei) {
    int e = blockIdx.x * blockDim.x + threadIdx.x;
    if (e >= NE) return;
    int sidx = edge_val(ei, e);
    int d    = edge_val(ei, (long long)NE + e);
    int p = atomicAdd(&g_cursor[d], 1);
    g_col[p] = sidx;
}

// ---------------- aggregation: warp per node, float4 per lane --------------
__global__ void __launch_bounds__(256) k_agg(const float4* __restrict__ xin,
                                             float4* __restrict__ xout) {
    int w = (blockIdx.x << 3) + (threadIdx.x >> 5);   // node
    if (w >= NV) return;
    int lane = threadIdx.x & 31;
    float dv = g_dinv[w];
    float4 xv = xin[(size_t)w * 32 + lane];
    float4 acc;
    float dvv = dv * dv;
    acc.x = dvv * xv.x; acc.y = dvv * xv.y; acc.z = dvv * xv.z; acc.w = dvv * xv.w;
    int e  = g_rowptr[w];
    int e1 = g_rowptr[w + 1];
    for (; e + 3 < e1; e += 4) {
        int s0 = g_col[e],     s1 = g_col[e + 1];
        int s2 = g_col[e + 2], s3 = g_col[e + 3];
        float w0 = dv * g_dinv[s0], w1 = dv * g_dinv[s1];
        float w2 = dv * g_dinv[s2], w3 = dv * g_dinv[s3];
        float4 v0 = xin[(size_t)s0 * 32 + lane];
        float4 v1 = xin[(size_t)s1 * 32 + lane];
        float4 v2 = xin[(size_t)s2 * 32 + lane];
        float4 v3 = xin[(size_t)s3 * 32 + lane];
        acc.x += w0 * v0.x + w1 * v1.x + w2 * v2.x + w3 * v3.x;
        acc.y += w0 * v0.y + w1 * v1.y + w2 * v2.y + w3 * v3.y;
        acc.z += w0 * v0.z + w1 * v1.z + w2 * v2.z + w3 * v3.z;
        acc.w += w0 * v0.w + w1 * v1.w + w2 * v2.w + w3 * v3.w;
    }
    for (; e < e1; e++) {
        int s = g_col[e];
        float ws = dv * g_dinv[s];
        float4 v = xin[(size_t)s * 32 + lane];
        acc.x += ws * v.x; acc.y += ws * v.y; acc.z += ws * v.z; acc.w += ws * v.w;
    }
    xout[(size_t)w * 32 + lane] = acc;
}

// ---------------- cp.async helpers ----------------
__device__ __forceinline__ void cp16(void* dst, const void* src, bool pred) {
    unsigned int d = (unsigned int)__cvta_generic_to_shared(dst);
    int sz = pred ? 16 : 0;
    asm volatile("cp.async.cg.shared.global [%0], [%1], 16, %2;"
                 :: "r"(d), "l"(src), "r"(sz));
}
__device__ __forceinline__ void cp_commit() {
    asm volatile("cp.async.commit_group;");
}
template <int N>
__device__ __forceinline__ void cp_wait() {
    asm volatile("cp.async.wait_group %0;" :: "n"(N));
}

// ---------------- TF32 tensor GEMM, cp.async double-buffered ---------------
// Block tile 128x128, BK=16, 2 stages. 8 warps (4 M x 2 N), warp tile 32x64.
template <bool RELU>
__global__ void __launch_bounds__(256, 2) k_tgemm(const float* __restrict__ A,
                                                  const float* __restrict__ B,
                                                  const float* __restrict__ bias,
                                                  float* __restrict__ C,
                                                  int M, int K, int N) {
    constexpr int BM = 128, BN = 128, BK = 16;
    constexpr int LDA = BK + 4;   // 20 floats (80B rows, 16B aligned)
    constexpr int LDB = BN + 4;   // 132
    constexpr int ASZ = BM * LDA; // 2560 floats / stage
    constexpr int BSZ = BK * LDB; // 2112 floats / stage
    __shared__ float smem[2 * ASZ + 2 * BSZ];   // 37376 B
    float* As = smem;
    float* Bs = smem + 2 * ASZ;

    int tid  = threadIdx.x;
    int warp = tid >> 5;
    int lane = tid & 31;
    int m0 = blockIdx.y * BM, n0 = blockIdx.x * BN;
    int wm = warp & 3, wn = warp >> 2;

    wmma::fragment<wmma::accumulator, 16, 16, 8, float> acc[2][4];
#pragma unroll
    for (int i = 0; i < 2; i++)
#pragma unroll
        for (int j = 0; j < 4; j++) wmma::fill_fragment(acc[i][j], 0.0f);

    int KT = K / BK;

    auto load_tile = [&](int t, int buf) {
        int k0 = t * BK;
        float* Ab = As + buf * ASZ;
        float* Bb = Bs + buf * BSZ;
#pragma unroll
        for (int i = 0; i < 2; i++) {
            int idx = tid + 256 * i;
            int r = idx >> 2, c = (idx & 3) * 4;
            bool ok = (m0 + r) < M;
            cp16(&Ab[r * LDA + c], &A[(size_t)(m0 + r) * K + k0 + c], ok);
        }
#pragma unroll
        for (int i = 0; i < 2; i++) {
            int idx = tid + 256 * i;
            int r = idx >> 5, c = (idx & 31) * 4;
            cp16(&Bb[r * LDB + c], &B[(size_t)(k0 + r) * N + n0 + c], true);
        }
        cp_commit();
    };

    load_tile(0, 0);
    for (int t = 0; t < KT; t++) {
        int cur = t & 1;
        if (t + 1 < KT) {
            load_tile(t + 1, cur ^ 1);
            cp_wait<1>();
        } else {
            cp_wait<0>();
        }
        __syncthreads();
        float* Ab = As + cur * ASZ;
        float* Bb = Bs + cur * BSZ;
#pragma unroll
        for (int kk = 0; kk < BK; kk += 8) {
            wmma::fragment<wmma::matrix_a, 16, 16, 8, wmma::precision::tf32,
                           wmma::row_major> af[2];
            wmma::fragment<wmma::matrix_b, 16, 16, 8, wmma::precision::tf32,
                           wmma::row_major> bf[4];
#pragma unroll
            for (int i = 0; i < 2; i++)
                wmma::load_matrix_sync(af[i], &Ab[(wm * 32 + i * 16) * LDA + kk], LDA);
#pragma unroll
            for (int j = 0; j < 4; j++)
                wmma::load_matrix_sync(bf[j], &Bb[kk * LDB + wn * 64 + j * 16], LDB);
#pragma unroll
            for (int i = 0; i < 2; i++)
#pragma unroll
                for (int j = 0; j < 4; j++)
                    wmma::mma_sync(acc[i][j], af[i], bf[j], acc[i][j]);
        }
        __syncthreads();
    }

    // epilogue: reuse smem as per-warp staging (16x16, ld=20)
    float* stage = smem + warp * 320;
#pragma unroll
    for (int i = 0; i < 2; i++) {
#pragma unroll
        for (int j = 0; j < 4; j++) {
            wmma::store_matrix_sync(stage, acc[i][j], 20, wmma::mem_row_major);
            __syncwarp();
            int r  = lane >> 1;
            int cs = (lane & 1) * 8;
            int gm = m0 + wm * 32 + i * 16 + r;
            int gn = n0 + wn * 64 + j * 16 + cs;
            if (gm < M) {
                const float* sp = &stage[r * 20 + cs];
                float4 o0, o1;
                o0.x = sp[0] + bias[gn + 0]; o0.y = sp[1] + bias[gn + 1];
                o0.z = sp[2] + bias[gn + 2]; o0.w = sp[3] + bias[gn + 3];
                o1.x = sp[4] + bias[gn + 4]; o1.y = sp[5] + bias[gn + 5];
                o1.z = sp[6] + bias[gn + 6]; o1.w = sp[7] + bias[gn + 7];
                if (RELU) {
                    o0.x = fmaxf(o0.x, 0.f); o0.y = fmaxf(o0.y, 0.f);
                    o0.z = fmaxf(o0.z, 0.f); o0.w = fmaxf(o0.w, 0.f);
                    o1.x = fmaxf(o1.x, 0.f); o1.y = fmaxf(o1.y, 0.f);
                    o1.z = fmaxf(o1.z, 0.f); o1.w = fmaxf(o1.w, 0.f);
                }
                *(float4*)&C[(size_t)gm * N + gn]     = o0;
                *(float4*)&C[(size_t)gm * N + gn + 4] = o1;
            }
            __syncwarp();
        }
    }
}

// ---------------- final projection 512 -> 3 ----------------
__global__ void __launch_bounds__(256) k_out3(const float* __restrict__ h,
                                              const float* __restrict__ Wc,
                                              const float* __restrict__ bc,
                                              float* __restrict__ out) {
    __shared__ float wc[512 * 3];
    for (int i = threadIdx.x; i < 512 * 3; i += blockDim.x) wc[i] = Wc[i];
    __syncthreads();
    int gw   = (blockIdx.x * blockDim.x + threadIdx.x) >> 5;
    int lane = threadIdx.x & 31;
    if (gw >= NV) return;
    float a0 = 0.f, a1 = 0.f, a2 = 0.f;
#pragma unroll
    for (int i = 0; i < 16; i++) {
        int k = lane + 32 * i;
        float hv = h[gw * 512 + k];
        a0 += hv * wc[k * 3 + 0];
        a1 += hv * wc[k * 3 + 1];
        a2 += hv * wc[k * 3 + 2];
    }
#pragma unroll
    for (int o = 16; o; o >>= 1) {
        a0 += __shfl_xor_sync(0xFFFFFFFFu, a0, o);
        a1 += __shfl_xor_sync(0xFFFFFFFFu, a1, o);
        a2 += __shfl_xor_sync(0xFFFFFFFFu, a2, o);
    }
    if (lane == 0) {
        out[gw * 3 + 0] = a0 + bc[0];
        out[gw * 3 + 1] = a1 + bc[1];
        out[gw * 3 + 2] = a2 + bc[2];
    }
}

// ---------------- launch ----------------
extern "C" void kernel_launch(void* const* d_in, const int* in_sizes, int n_in,
                              void* d_out, int out_size) {
    const float* x  = (const float*)d_in[0];
    const void*  ei = d_in[1];
    const float* W1 = (const float*)d_in[2];
    const float* b1 = (const float*)d_in[3];
    const float* W2 = (const float*)d_in[4];
    const float* b2 = (const float*)d_in[5];
    const float* W3 = (const float*)d_in[6];
    const float* b3 = (const float*)d_in[7];
    const float* Wi = (const float*)d_in[8];
    const float* bi = (const float*)d_in[9];
    const float* Wc = (const float*)d_in[10];
    const float* bc = (const float*)d_in[11];
    float* out = (float*)d_out;

    float *pA, *pH, *pX1, *pX2;
    cudaGetSymbolAddress((void**)&pA,  g_a);
    cudaGetSymbolAddress((void**)&pH,  g_h);
    cudaGetSymbolAddress((void**)&pX1, g_x1);
    cudaGetSymbolAddress((void**)&pX2, g_x2);

    const int TB  = 256;
    const int NEB = (NE + TB - 1) / TB;
    const int MT  = (NV + 127) / 128;
    const int AGB = (NV + 7) / 8;

    // preprocessing
    k_init_detect<<<NBLK, TB>>>((const int*)ei);
    k_hist<<<NEB, TB>>>(ei);
    k_reduce<<<NBLK, TB>>>();
    k_scanb<<<1, 512>>>();
    k_scatter<<<NBLK, TB>>>();
    k_fill<<<NEB, TB>>>(ei);

    // layer 1
    k_agg<<<AGB, TB>>>((const float4*)x, (float4*)pA);
    k_tgemm<true><<<dim3(1, MT), 256>>>(pA, W1, b1, pH, NV, 128, 128);
    // layer 2
    k_agg<<<AGB, TB>>>((const float4*)pH, (float4*)pA);
    k_tgemm<true><<<dim3(1, MT), 256>>>(pA, W2, b2, pH, NV, 128, 128);
    // layer 3: agg 128-dim, project 128->512
    k_agg<<<AGB, TB>>>((const float4*)pH, (float4*)pA);
    k_tgemm<true><<<dim3(4, MT), 256>>>(pA, W3, b3, pX1, NV, 128, 512);
    // MLP 512->512
    k_tgemm<true><<<dim3(4, MT), 256>>>(pX1, Wi, bi, pX2, NV, 512, 512);
    // classifier
    k_out3<<<(NV * 32 + TB - 1) / TB, TB>>>(pX2, Wc, bc, out);
}